// round 1
// baseline (speedup 1.0000x reference)
#include <cuda_runtime.h>
#include <cuda_bf16.h>

// Problem constants
constexpr int B_  = 2;
constexpr int T_  = 2048;
constexpr int C_  = 1024;
constexpr int H_  = 16;
constexpr int HS_ = 64;
constexpr int M_  = B_ * T_;      // 4096 rows
constexpr int N1_ = 3 * C_;       // 3072 (qkv cols)

// Scratch (device globals: allocation-free rule)
__device__ float g_qkv[M_ * N1_];   // [4096, 3072]  order: K | Q | V segments
__device__ float g_att[M_ * C_];    // [4096, 1024]  attention output (pre-proj)

// ---------------------------------------------------------------------------
// f32x2 helpers (FFMA2 — 2x fp32 throughput on sm_100+; ptxas never emits this)
// ---------------------------------------------------------------------------
__device__ __forceinline__ unsigned long long pack2(float lo, float hi) {
    unsigned long long r;
    asm("mov.b64 %0, {%1, %2};" : "=l"(r) : "f"(lo), "f"(hi));
    return r;
}
__device__ __forceinline__ void unpack2(unsigned long long v, float& lo, float& hi) {
    asm("mov.b64 {%0, %1}, %2;" : "=f"(lo), "=f"(hi) : "l"(v));
}
__device__ __forceinline__ void fma2(unsigned long long& d,
                                     unsigned long long a,
                                     unsigned long long b) {
    asm("fma.rn.f32x2 %0, %1, %2, %0;" : "+l"(d) : "l"(a), "l"(b));
}

// ---------------------------------------------------------------------------
// SGEMM: C[M,N] = A[M,K] @ B[K,N], all row-major, dims divisible by tile.
// 128x128x8 tile, 256 threads, 8x8 micro-tile per thread, f32x2 inner loop.
// ---------------------------------------------------------------------------
__global__ __launch_bounds__(256)
void sgemm_f32x2_kernel(const float* __restrict__ A,
                        const float* __restrict__ Bm,
                        float* __restrict__ Cm,
                        int M, int N, int K)
{
    constexpr int BM = 128, BN = 128, BK = 8;
    __shared__ float As[BK][BM];   // A tile stored transposed: As[k][m]
    __shared__ float Bs[BK][BN];   // Bs[k][n]

    const int tid = threadIdx.x;
    const int tx  = tid & 15;      // 0..15 -> 8-col group
    const int ty  = tid >> 4;      // 0..15 -> 8-row group
    const int bm  = blockIdx.y * BM;
    const int bn  = blockIdx.x * BN;

    // Loaders: A tile 128x8 (one float4 per thread), B tile 8x128
    const int arow = tid >> 1;             // 0..127
    const int acol = (tid & 1) * 4;        // 0 or 4
    const int brow = tid >> 5;             // 0..7
    const int bcol = (tid & 31) * 4;       // 0..124

    const float* Ap = A  + (size_t)(bm + arow) * K + acol;
    const float* Bp = Bm + (size_t)brow * N + bn + bcol;

    unsigned long long acc[8][4];
    #pragma unroll
    for (int i = 0; i < 8; i++)
        #pragma unroll
        for (int j = 0; j < 4; j++) acc[i][j] = 0ULL;   // (0.0f, 0.0f)

    for (int k0 = 0; k0 < K; k0 += BK) {
        float4 av = *(const float4*)Ap;
        float4 bv = *(const float4*)Bp;
        As[acol + 0][arow] = av.x;
        As[acol + 1][arow] = av.y;
        As[acol + 2][arow] = av.z;
        As[acol + 3][arow] = av.w;
        *(float4*)&Bs[brow][bcol] = bv;
        __syncthreads();

        #pragma unroll
        for (int kk = 0; kk < BK; kk++) {
            float4 a0 = *(const float4*)&As[kk][ty * 8];
            float4 a1 = *(const float4*)&As[kk][ty * 8 + 4];
            ulonglong2 bb0 = *(const ulonglong2*)&Bs[kk][tx * 8];
            ulonglong2 bb1 = *(const ulonglong2*)&Bs[kk][tx * 8 + 4];
            unsigned long long b2[4] = { bb0.x, bb0.y, bb1.x, bb1.y };
            float ar[8] = { a0.x, a0.y, a0.z, a0.w, a1.x, a1.y, a1.z, a1.w };
            #pragma unroll
            for (int i = 0; i < 8; i++) {
                unsigned long long ad = pack2(ar[i], ar[i]);
                fma2(acc[i][0], ad, b2[0]);
                fma2(acc[i][1], ad, b2[1]);
                fma2(acc[i][2], ad, b2[2]);
                fma2(acc[i][3], ad, b2[3]);
            }
        }
        __syncthreads();
        Ap += BK;
        Bp += (size_t)BK * N;
    }

    #pragma unroll
    for (int i = 0; i < 8; i++) {
        float o[8];
        #pragma unroll
        for (int jp = 0; jp < 4; jp++) unpack2(acc[i][jp], o[jp * 2], o[jp * 2 + 1]);
        float* cp = Cm + (size_t)(bm + ty * 8 + i) * N + bn + tx * 8;
        *(float4*)cp       = make_float4(o[0], o[1], o[2], o[3]);
        *(float4*)(cp + 4) = make_float4(o[4], o[5], o[6], o[7]);
    }
}

// ---------------------------------------------------------------------------
// Causal flash attention, fp32.
// Grid: (T/64, B*H). Block 256 threads (16x16); thread (ty,tx) owns
// S/O micro-tile rows 4*ty..+3, cols 4*tx..+3. Per-row softmax stats are
// replicated across the 16 tx lanes (shfl-butterfly over lane bits 0..3).
// qkv layout: [B, T, 3C], column segments: K=[0,C), Q=[C,2C), V=[2C,3C).
// ---------------------------------------------------------------------------
constexpr int LDQ = 68;  // padded stride for QT / K-P buffer
constexpr int ATT_SMEM_FLOATS = 64 * LDQ + 64 * LDQ + 64 * 64;
constexpr int ATT_SMEM_BYTES  = ATT_SMEM_FLOATS * 4;   // 51200

__global__ __launch_bounds__(256)
void attn_flash_kernel(const float* __restrict__ qkv, float* __restrict__ outp)
{
    extern __shared__ float sm[];
    float* QT = sm;                 // [64][LDQ]  QT[d][r] (Q transposed)
    float* KP = sm + 64 * LDQ;      // K transposed [d][r], reused for P [r][c]
    float* Vs = sm + 2 * 64 * LDQ;  // [64][64]   Vs[k][d]

    const int qb = gridDim.x - 1 - blockIdx.x;   // heavy blocks first
    const int bh = blockIdx.y;
    const int b  = bh >> 4;
    const int h  = bh & 15;

    const int tid = threadIdx.x;
    const int tx  = tid & 15;
    const int ty  = tid >> 4;

    const int ldr = tid >> 4;          // loader token row base 0..15
    const int ldd = (tid & 15) * 4;    // loader dim 0,4,...,60

    const size_t qrow0 = (size_t)(b * T_ + qb * 64) * N1_;

    // Load Q tile transposed
    #pragma unroll
    for (int u = 0; u < 4; u++) {
        int r = u * 16 + ldr;
        float4 v = *(const float4*)(qkv + qrow0 + (size_t)r * N1_ + C_ + h * HS_ + ldd);
        QT[(ldd + 0) * LDQ + r] = v.x;
        QT[(ldd + 1) * LDQ + r] = v.y;
        QT[(ldd + 2) * LDQ + r] = v.z;
        QT[(ldd + 3) * LDQ + r] = v.w;
    }

    float m_i[4], l_i[4], acc[4][4];
    #pragma unroll
    for (int i = 0; i < 4; i++) {
        m_i[i] = -1e30f; l_i[i] = 0.0f;
        #pragma unroll
        for (int j = 0; j < 4; j++) acc[i][j] = 0.0f;
    }

    for (int kb = 0; kb <= qb; kb++) {
        __syncthreads();   // prev P@V reads done; Q stores visible (first iter)

        const size_t krow0 = (size_t)(b * T_ + kb * 64) * N1_;
        #pragma unroll
        for (int u = 0; u < 4; u++) {
            int r = u * 16 + ldr;
            float4 kv = *(const float4*)(qkv + krow0 + (size_t)r * N1_ + h * HS_ + ldd);
            KP[(ldd + 0) * LDQ + r] = kv.x;
            KP[(ldd + 1) * LDQ + r] = kv.y;
            KP[(ldd + 2) * LDQ + r] = kv.z;
            KP[(ldd + 3) * LDQ + r] = kv.w;
            float4 vv = *(const float4*)(qkv + krow0 + (size_t)r * N1_ + 2 * C_ + h * HS_ + ldd);
            *(float4*)&Vs[r * 64 + ldd] = vv;
        }
        __syncthreads();

        // S = Q @ K^T  (per-thread 4x4)
        float s[4][4];
        #pragma unroll
        for (int i = 0; i < 4; i++)
            #pragma unroll
            for (int j = 0; j < 4; j++) s[i][j] = 0.0f;

        #pragma unroll 4
        for (int d = 0; d < 64; d++) {
            float4 qv = *(const float4*)&QT[d * LDQ + ty * 4];
            float4 kv = *(const float4*)&KP[d * LDQ + tx * 4];
            float qa[4] = { qv.x, qv.y, qv.z, qv.w };
            float ka[4] = { kv.x, kv.y, kv.z, kv.w };
            #pragma unroll
            for (int i = 0; i < 4; i++)
                #pragma unroll
                for (int j = 0; j < 4; j++)
                    s[i][j] = fmaf(qa[i], ka[j], s[i][j]);
        }

        const float sc = 0.03125f;   // 1024^-0.5
        if (kb == qb) {
            #pragma unroll
            for (int i = 0; i < 4; i++)
                #pragma unroll
                for (int j = 0; j < 4; j++) {
                    int qi = ty * 4 + i, kj = tx * 4 + j;
                    s[i][j] = (kj <= qi) ? s[i][j] * sc : -1e30f;
                }
        } else {
            #pragma unroll
            for (int i = 0; i < 4; i++)
                #pragma unroll
                for (int j = 0; j < 4; j++) s[i][j] *= sc;
        }

        __syncthreads();   // all threads done reading KP as K

        // Online softmax; write P into KP buffer
        #pragma unroll
        for (int i = 0; i < 4; i++) {
            float tm = fmaxf(fmaxf(s[i][0], s[i][1]), fmaxf(s[i][2], s[i][3]));
            #pragma unroll
            for (int o = 1; o < 16; o <<= 1)
                tm = fmaxf(tm, __shfl_xor_sync(0xffffffffu, tm, o));
            float mn    = fmaxf(m_i[i], tm);
            float scale = __expf(m_i[i] - mn);
            m_i[i] = mn;
            float p[4], rs = 0.0f;
            #pragma unroll
            for (int j = 0; j < 4; j++) { p[j] = __expf(s[i][j] - mn); rs += p[j]; }
            #pragma unroll
            for (int o = 1; o < 16; o <<= 1)
                rs += __shfl_xor_sync(0xffffffffu, rs, o);
            l_i[i] = l_i[i] * scale + rs;
            #pragma unroll
            for (int j = 0; j < 4; j++) acc[i][j] *= scale;
            *(float4*)&KP[(ty * 4 + i) * LDQ + tx * 4] = make_float4(p[0], p[1], p[2], p[3]);
        }
        __syncthreads();

        // O += P @ V
        #pragma unroll 4
        for (int k = 0; k < 64; k++) {
            float4 vv = *(const float4*)&Vs[k * 64 + tx * 4];
            float va[4] = { vv.x, vv.y, vv.z, vv.w };
            #pragma unroll
            for (int i = 0; i < 4; i++) {
                float pv = KP[(ty * 4 + i) * LDQ + k];
                #pragma unroll
                for (int j = 0; j < 4; j++)
                    acc[i][j] = fmaf(pv, va[j], acc[i][j]);
            }
        }
    }

    // Normalize + write [B,T,C] with head offset
    #pragma unroll
    for (int i = 0; i < 4; i++) {
        float inv = 1.0f / l_i[i];
        int row = qb * 64 + ty * 4 + i;
        float* op = outp + (size_t)(b * T_ + row) * C_ + h * HS_ + tx * 4;
        *(float4*)op = make_float4(acc[i][0] * inv, acc[i][1] * inv,
                                   acc[i][2] * inv, acc[i][3] * inv);
    }
}

// ---------------------------------------------------------------------------
// Launch
// ---------------------------------------------------------------------------
extern "C" void kernel_launch(void* const* d_in, const int* in_sizes, int n_in,
                              void* d_out, int out_size)
{
    // Identify inputs by element count (all distinct)
    const float* X = nullptr; const float* Wqkv = nullptr; const float* Wproj = nullptr;
    for (int i = 0; i < n_in; i++) {
        if      (in_sizes[i] == M_ * C_)   X     = (const float*)d_in[i];
        else if (in_sizes[i] == C_ * N1_)  Wqkv  = (const float*)d_in[i];
        else if (in_sizes[i] == C_ * C_)   Wproj = (const float*)d_in[i];
    }
    float* out = (float*)d_out;

    float* qkv_buf = nullptr;
    float* att_buf = nullptr;
    cudaGetSymbolAddress((void**)&qkv_buf, g_qkv);
    cudaGetSymbolAddress((void**)&att_buf, g_att);

    cudaFuncSetAttribute(attn_flash_kernel,
                         cudaFuncAttributeMaxDynamicSharedMemorySize, ATT_SMEM_BYTES);

    dim3 blk(256);
    // 1) qkv = X @ W_qkv   [4096,1024]x[1024,3072]
    sgemm_f32x2_kernel<<<dim3(N1_ / 128, M_ / 128), blk>>>(X, Wqkv, qkv_buf, M_, N1_, C_);
    // 2) attention -> att_buf [4096,1024]
    attn_flash_kernel<<<dim3(T_ / 64, B_ * H_), blk, ATT_SMEM_BYTES>>>(qkv_buf, att_buf);
    // 3) out = att @ W_proj [4096,1024]x[1024,1024]
    sgemm_f32x2_kernel<<<dim3(C_ / 128, M_ / 128), blk>>>(att_buf, Wproj, out, M_, C_, C_);
}

// round 3
// speedup vs baseline: 1.5249x; 1.5249x over previous
#include <cuda_runtime.h>
#include <cuda_bf16.h>

// Problem constants
constexpr int B_  = 2;
constexpr int T_  = 2048;
constexpr int C_  = 1024;
constexpr int H_  = 16;
constexpr int HS_ = 64;
constexpr int M_  = B_ * T_;      // 4096
constexpr int N1_ = 3 * C_;       // 3072
constexpr int KB_ = 3 * C_;       // split-K' = 3072

// Scratch (device globals: allocation-free rule)
__device__ float g_qkv[M_ * N1_];            // fp32 qkv  [4096,3072]  (K|Q|V)
__device__ float g_att[M_ * C_];             // fp32 attention out [4096,1024]
__device__ __nv_bfloat16 g_Xc  [M_  * KB_];  // X split   [4096,3072]  (hi|hi|lo)
__device__ __nv_bfloat16 g_attc[M_  * KB_];  // att split [4096,3072]
__device__ __nv_bfloat16 g_Wqc [N1_ * KB_];  // W_qkv^T split [3072,3072] (hi|lo|hi)
__device__ __nv_bfloat16 g_Wpc [C_  * KB_];  // W_proj^T split [1024,3072]

// ---------------------------------------------------------------------------
// PTX helpers (all baseline-ISA: work on compute_103 virtual arch)
// ---------------------------------------------------------------------------
__device__ __forceinline__ unsigned long long pack2(float lo, float hi) {
    unsigned long long r;
    asm("mov.b64 %0, {%1, %2};" : "=l"(r) : "f"(lo), "f"(hi));
    return r;
}
__device__ __forceinline__ void unpack2(unsigned long long v, float& lo, float& hi) {
    asm("mov.b64 {%0, %1}, %2;" : "=f"(lo), "=f"(hi) : "l"(v));
}
__device__ __forceinline__ void fma2(unsigned long long& d,
                                     unsigned long long a, unsigned long long b) {
    asm("fma.rn.f32x2 %0, %1, %2, %0;" : "+l"(d) : "l"(a), "l"(b));
}
__device__ __forceinline__ void mul2(unsigned long long& d, unsigned long long a) {
    asm("mul.rn.f32x2 %0, %0, %1;" : "+l"(d) : "l"(a));
}
__device__ __forceinline__ unsigned smem_u32(const void* p) {
    unsigned a;
    asm("{ .reg .u64 t; cvta.to.shared.u64 t, %1; cvt.u32.u64 %0, t; }" : "=r"(a) : "l"(p));
    return a;
}
__device__ __forceinline__ void ldm4(unsigned* r, unsigned addr) {
    asm volatile("ldmatrix.sync.aligned.m8n8.x4.shared.b16 {%0,%1,%2,%3}, [%4];"
                 : "=r"(r[0]), "=r"(r[1]), "=r"(r[2]), "=r"(r[3]) : "r"(addr));
}
__device__ __forceinline__ void mma_bf16(float* c, const unsigned* a,
                                         unsigned b0, unsigned b1) {
    asm volatile("mma.sync.aligned.m16n8k16.row.col.f32.bf16.bf16.f32 "
                 "{%0,%1,%2,%3}, {%4,%5,%6,%7}, {%8,%9}, {%0,%1,%2,%3};"
                 : "+f"(c[0]), "+f"(c[1]), "+f"(c[2]), "+f"(c[3])
                 : "r"(a[0]), "r"(a[1]), "r"(a[2]), "r"(a[3]), "r"(b0), "r"(b1));
}

// ---------------------------------------------------------------------------
// Conversion kernels: fp32 -> bf16 hi/lo split
// ---------------------------------------------------------------------------
__global__ __launch_bounds__(256)
void conv_split_kernel(const float* __restrict__ in, __nv_bfloat16* __restrict__ out)
{
    int i4 = blockIdx.x * blockDim.x + threadIdx.x;   // over M_*C_/4
    int r  = i4 >> 8;
    int c4 = (i4 & 255) * 4;
    float4 v = *(const float4*)(in + (size_t)r * C_ + c4);
    __nv_bfloat16 hx = __float2bfloat16_rn(v.x), hy = __float2bfloat16_rn(v.y);
    __nv_bfloat16 hz = __float2bfloat16_rn(v.z), hw = __float2bfloat16_rn(v.w);
    __nv_bfloat162 h01 = __halves2bfloat162(hx, hy);
    __nv_bfloat162 h23 = __halves2bfloat162(hz, hw);
    __nv_bfloat162 l01 = __halves2bfloat162(
        __float2bfloat16_rn(v.x - __bfloat162float(hx)),
        __float2bfloat16_rn(v.y - __bfloat162float(hy)));
    __nv_bfloat162 l23 = __halves2bfloat162(
        __float2bfloat16_rn(v.z - __bfloat162float(hz)),
        __float2bfloat16_rn(v.w - __bfloat162float(hw)));
    size_t ob = (size_t)r * KB_ + c4;
    *(__nv_bfloat162*)(out + ob)              = h01;
    *(__nv_bfloat162*)(out + ob + 2)          = h23;
    *(__nv_bfloat162*)(out + ob + C_)         = h01;
    *(__nv_bfloat162*)(out + ob + C_ + 2)     = h23;
    *(__nv_bfloat162*)(out + ob + 2 * C_)     = l01;
    *(__nv_bfloat162*)(out + ob + 2 * C_ + 2) = l23;
}

// W [K,N] row-major -> out [N, 3K] bf16 with blocks [hi | lo | hi] along K
__global__ __launch_bounds__(256)
void conv_wT_kernel(const float* __restrict__ in, __nv_bfloat16* __restrict__ out,
                    int K, int N)
{
    __shared__ float ts[32][33];
    int n0 = blockIdx.x * 32, k0 = blockIdx.y * 32;
    int tx = threadIdx.x, ty = threadIdx.y;  // 32x8
    #pragma unroll
    for (int i = 0; i < 32; i += 8)
        ts[ty + i][tx] = in[(size_t)(k0 + ty + i) * N + n0 + tx];
    __syncthreads();
    #pragma unroll
    for (int i = 0; i < 32; i += 8) {
        int n = n0 + ty + i, k = k0 + tx;
        float v = ts[tx][ty + i];
        __nv_bfloat16 h = __float2bfloat16_rn(v);
        __nv_bfloat16 l = __float2bfloat16_rn(v - __bfloat162float(h));
        size_t ob = (size_t)n * KB_;
        out[ob + k]         = h;
        out[ob + K + k]     = l;
        out[ob + 2 * K + k] = h;
    }
}

// ---------------------------------------------------------------------------
// Tensor-core GEMM via mma.sync (bf16, fp32 accum):
//   C[M,N] = A'[M,KB] @ B'[N,KB]^T  (A row-major, B' is N x K row-major = col-major B)
// 128x128 CTA tile, BK=32, 8 warps (2x4), warp tile 64x32.
// ---------------------------------------------------------------------------
constexpr int LDA_ = 40;   // bf16 stride (80B): conflict-free ldmatrix

__global__ __launch_bounds__(256)
void gemm_mma_kernel(const __nv_bfloat16* __restrict__ A,
                     const __nv_bfloat16* __restrict__ Bm,
                     float* __restrict__ Cm, int N)
{
    __shared__ __align__(16) __nv_bfloat16 smA[2][128 * LDA_];
    __shared__ __align__(16) __nv_bfloat16 smB[2][128 * LDA_];

    const int tid = threadIdx.x, lane = tid & 31, wid = tid >> 5;
    const int wm = (wid & 1) * 64, wn = (wid >> 1) * 32;
    const int bm = blockIdx.y * 128, bn = blockIdx.x * 128;

    const __nv_bfloat16* Ag = A  + (size_t)bm * KB_;
    const __nv_bfloat16* Bg = Bm + (size_t)bn * KB_;

    const int lr = tid >> 2, lseg = tid & 3;     // loader: row 0..63(+64), 16B seg

    float acc[4][4][4] = {};

    // prologue: k-tile 0 -> buffer 0
    #pragma unroll
    for (int u = 0; u < 2; u++) {
        int row = lr + u * 64;
        *(uint4*)&smA[0][row * LDA_ + lseg * 8] =
            *(const uint4*)(Ag + (size_t)row * KB_ + lseg * 8);
        *(uint4*)&smB[0][row * LDA_ + lseg * 8] =
            *(const uint4*)(Bg + (size_t)row * KB_ + lseg * 8);
    }
    __syncthreads();

    const unsigned baseA[2] = { smem_u32(smA[0]), smem_u32(smA[1]) };
    const unsigned baseB[2] = { smem_u32(smB[0]), smem_u32(smB[1]) };
    const int ar = lane & 15, ah = lane >> 4;    // A frag: row, k-half
    const int bg = lane >> 3, bi = lane & 7;     // B frag: group, row

    constexpr int NK = KB_ / 32;                 // 96
    for (int kt = 0; kt < NK; kt++) {
        const int cur = kt & 1, nxt = cur ^ 1;
        uint4 ra[2], rb[2];
        const bool pf = (kt + 1 < NK);
        if (pf) {
            const int kpos = (kt + 1) * 32;
            #pragma unroll
            for (int u = 0; u < 2; u++) {
                int row = lr + u * 64;
                ra[u] = *(const uint4*)(Ag + (size_t)row * KB_ + kpos + lseg * 8);
                rb[u] = *(const uint4*)(Bg + (size_t)row * KB_ + kpos + lseg * 8);
            }
        }

        #pragma unroll
        for (int ks = 0; ks < 2; ks++) {
            unsigned afr[4][4], bfr[2][4];
            #pragma unroll
            for (int mt = 0; mt < 4; mt++) {
                unsigned ad = baseA[cur] +
                    ((wm + mt * 16 + ar) * LDA_ + ks * 16 + ah * 8) * 2;
                ldm4(afr[mt], ad);
            }
            #pragma unroll
            for (int p = 0; p < 2; p++) {
                unsigned bd = baseB[cur] +
                    ((wn + p * 16 + (bg >> 1) * 8 + bi) * LDA_ + ks * 16 + (bg & 1) * 8) * 2;
                ldm4(bfr[p], bd);
            }
            #pragma unroll
            for (int mt = 0; mt < 4; mt++)
                #pragma unroll
                for (int ng = 0; ng < 4; ng++)
                    mma_bf16(acc[mt][ng], afr[mt],
                             bfr[ng >> 1][(ng & 1) * 2], bfr[ng >> 1][(ng & 1) * 2 + 1]);
        }

        if (pf) {
            #pragma unroll
            for (int u = 0; u < 2; u++) {
                int row = lr + u * 64;
                *(uint4*)&smA[nxt][row * LDA_ + lseg * 8] = ra[u];
                *(uint4*)&smB[nxt][row * LDA_ + lseg * 8] = rb[u];
            }
        }
        __syncthreads();
    }

    // Epilogue: acc -> C (fp32)
    #pragma unroll
    for (int mt = 0; mt < 4; mt++)
        #pragma unroll
        for (int ng = 0; ng < 4; ng++) {
            float* cp = Cm + (size_t)(bm + wm + mt * 16 + (lane >> 2)) * N
                           + bn + wn + ng * 8 + (lane & 3) * 2;
            *(float2*)cp                 = make_float2(acc[mt][ng][0], acc[mt][ng][1]);
            *(float2*)(cp + (size_t)8 * N) = make_float2(acc[mt][ng][2], acc[mt][ng][3]);
        }
}

// ---------------------------------------------------------------------------
// Causal flash attention, fp32 with f32x2 inner loops.
// Grid (T/64, B*H), 256 threads (16x16). qkv layout [B,T,3C]: K|Q|V.
// ---------------------------------------------------------------------------
constexpr int LDQ = 68;
constexpr int ATT_SMEM_BYTES = (64 * LDQ + 64 * LDQ + 64 * 64) * 4;  // 51200

__global__ __launch_bounds__(256)
void attn_flash_kernel(const float* __restrict__ qkv, float* __restrict__ outp)
{
    extern __shared__ float smf[];
    float* QT = smf;
    float* KP = smf + 64 * LDQ;
    float* Vs = smf + 2 * 64 * LDQ;

    const int qb = gridDim.x - 1 - blockIdx.x;
    const int bh = blockIdx.y;
    const int b  = bh >> 4;
    const int h  = bh & 15;

    const int tid = threadIdx.x;
    const int tx  = tid & 15;
    const int ty  = tid >> 4;
    const int ldr = tid >> 4;
    const int ldd = (tid & 15) * 4;

    const size_t qrow0 = (size_t)(b * T_ + qb * 64) * N1_;
    #pragma unroll
    for (int u = 0; u < 4; u++) {
        int r = u * 16 + ldr;
        float4 v = *(const float4*)(qkv + qrow0 + (size_t)r * N1_ + C_ + h * HS_ + ldd);
        QT[(ldd + 0) * LDQ + r] = v.x;
        QT[(ldd + 1) * LDQ + r] = v.y;
        QT[(ldd + 2) * LDQ + r] = v.z;
        QT[(ldd + 3) * LDQ + r] = v.w;
    }

    float m_i[4], l_i[4];
    unsigned long long acc2[4][2];
    #pragma unroll
    for (int i = 0; i < 4; i++) {
        m_i[i] = -1e30f; l_i[i] = 0.0f;
        acc2[i][0] = 0ULL; acc2[i][1] = 0ULL;
    }

    for (int kb = 0; kb <= qb; kb++) {
        __syncthreads();
        const size_t krow0 = (size_t)(b * T_ + kb * 64) * N1_;
        #pragma unroll
        for (int u = 0; u < 4; u++) {
            int r = u * 16 + ldr;
            float4 kv = *(const float4*)(qkv + krow0 + (size_t)r * N1_ + h * HS_ + ldd);
            KP[(ldd + 0) * LDQ + r] = kv.x;
            KP[(ldd + 1) * LDQ + r] = kv.y;
            KP[(ldd + 2) * LDQ + r] = kv.z;
            KP[(ldd + 3) * LDQ + r] = kv.w;
            float4 vv = *(const float4*)(qkv + krow0 + (size_t)r * N1_ + 2 * C_ + h * HS_ + ldd);
            *(float4*)&Vs[r * 64 + ldd] = vv;
        }
        __syncthreads();

        unsigned long long s2[4][2];
        #pragma unroll
        for (int i = 0; i < 4; i++) { s2[i][0] = 0ULL; s2[i][1] = 0ULL; }

        #pragma unroll 4
        for (int d = 0; d < 64; d++) {
            float4 qv = *(const float4*)&QT[d * LDQ + ty * 4];
            ulonglong2 kk = *(const ulonglong2*)&KP[d * LDQ + tx * 4];
            float qa[4] = { qv.x, qv.y, qv.z, qv.w };
            #pragma unroll
            for (int i = 0; i < 4; i++) {
                unsigned long long ad = pack2(qa[i], qa[i]);
                fma2(s2[i][0], ad, kk.x);
                fma2(s2[i][1], ad, kk.y);
            }
        }

        float s[4][4];
        #pragma unroll
        for (int i = 0; i < 4; i++) {
            unpack2(s2[i][0], s[i][0], s[i][1]);
            unpack2(s2[i][1], s[i][2], s[i][3]);
        }

        const float sc = 0.03125f;   // 1024^-0.5
        if (kb == qb) {
            #pragma unroll
            for (int i = 0; i < 4; i++)
                #pragma unroll
                for (int j = 0; j < 4; j++) {
                    int qi = ty * 4 + i, kj = tx * 4 + j;
                    s[i][j] = (kj <= qi) ? s[i][j] * sc : -1e30f;
                }
        } else {
            #pragma unroll
            for (int i = 0; i < 4; i++)
                #pragma unroll
                for (int j = 0; j < 4; j++) s[i][j] *= sc;
        }

        __syncthreads();

        #pragma unroll
        for (int i = 0; i < 4; i++) {
            float tm = fmaxf(fmaxf(s[i][0], s[i][1]), fmaxf(s[i][2], s[i][3]));
            #pragma unroll
            for (int o = 1; o < 16; o <<= 1)
                tm = fmaxf(tm, __shfl_xor_sync(0xffffffffu, tm, o));
            float mn    = fmaxf(m_i[i], tm);
            float scale = __expf(m_i[i] - mn);
            m_i[i] = mn;
            float p[4], rs = 0.0f;
            #pragma unroll
            for (int j = 0; j < 4; j++) { p[j] = __expf(s[i][j] - mn); rs += p[j]; }
            #pragma unroll
            for (int o = 1; o < 16; o <<= 1)
                rs += __shfl_xor_sync(0xffffffffu, rs, o);
            l_i[i] = l_i[i] * scale + rs;
            unsigned long long sp = pack2(scale, scale);
            mul2(acc2[i][0], sp);
            mul2(acc2[i][1], sp);
            *(float4*)&KP[(ty * 4 + i) * LDQ + tx * 4] = make_float4(p[0], p[1], p[2], p[3]);
        }
        __syncthreads();

        for (int k4 = 0; k4 < 64; k4 += 4) {
            float4 pr[4];
            #pragma unroll
            for (int i = 0; i < 4; i++)
                pr[i] = *(const float4*)&KP[(ty * 4 + i) * LDQ + k4];
            #pragma unroll
            for (int kk = 0; kk < 4; kk++) {
                ulonglong2 vv = *(const ulonglong2*)&Vs[(k4 + kk) * 64 + tx * 4];
                #pragma unroll
                for (int i = 0; i < 4; i++) {
                    float pv = (kk == 0) ? pr[i].x : (kk == 1) ? pr[i].y
                             : (kk == 2) ? pr[i].z : pr[i].w;
                    unsigned long long pd = pack2(pv, pv);
                    fma2(acc2[i][0], pd, vv.x);
                    fma2(acc2[i][1], pd, vv.y);
                }
            }
        }
    }

    #pragma unroll
    for (int i = 0; i < 4; i++) {
        float inv = 1.0f / l_i[i];
        float o0, o1, o2, o3;
        unpack2(acc2[i][0], o0, o1);
        unpack2(acc2[i][1], o2, o3);
        int row = qb * 64 + ty * 4 + i;
        float* op = outp + (size_t)(b * T_ + row) * C_ + h * HS_ + tx * 4;
        *(float4*)op = make_float4(o0 * inv, o1 * inv, o2 * inv, o3 * inv);
    }
}

// ---------------------------------------------------------------------------
// Launch
// ---------------------------------------------------------------------------
extern "C" void kernel_launch(void* const* d_in, const int* in_sizes, int n_in,
                              void* d_out, int out_size)
{
    const float* X = nullptr; const float* Wqkv = nullptr; const float* Wproj = nullptr;
    for (int i = 0; i < n_in; i++) {
        if      (in_sizes[i] == M_ * C_)   X     = (const float*)d_in[i];
        else if (in_sizes[i] == C_ * N1_)  Wqkv  = (const float*)d_in[i];
        else if (in_sizes[i] == C_ * C_)   Wproj = (const float*)d_in[i];
    }
    float* out = (float*)d_out;

    float *qkv_buf, *att_buf;
    __nv_bfloat16 *Xc, *attc, *Wqc, *Wpc;
    cudaGetSymbolAddress((void**)&qkv_buf, g_qkv);
    cudaGetSymbolAddress((void**)&att_buf, g_att);
    cudaGetSymbolAddress((void**)&Xc,   g_Xc);
    cudaGetSymbolAddress((void**)&attc, g_attc);
    cudaGetSymbolAddress((void**)&Wqc,  g_Wqc);
    cudaGetSymbolAddress((void**)&Wpc,  g_Wpc);

    cudaFuncSetAttribute(attn_flash_kernel,
                         cudaFuncAttributeMaxDynamicSharedMemorySize, ATT_SMEM_BYTES);

    // 1) split-convert inputs
    conv_split_kernel<<<M_ * C_ / 4 / 256, 256>>>(X, Xc);
    conv_wT_kernel<<<dim3(N1_ / 32, C_ / 32), dim3(32, 8)>>>(Wqkv, Wqc, C_, N1_);
    conv_wT_kernel<<<dim3(C_ / 32,  C_ / 32), dim3(32, 8)>>>(Wproj, Wpc, C_, C_);

    // 2) qkv = X @ W_qkv (mma.sync bf16 hi/lo split)
    gemm_mma_kernel<<<dim3(N1_ / 128, M_ / 128), 256>>>(Xc, Wqc, qkv_buf, N1_);

    // 3) attention
    attn_flash_kernel<<<dim3(T_ / 64, B_ * H_), 256, ATT_SMEM_BYTES>>>(qkv_buf, att_buf);

    // 4) split-convert attention output, then out = att @ W_proj
    conv_split_kernel<<<M_ * C_ / 4 / 256, 256>>>(att_buf, attc);
    gemm_mma_kernel<<<dim3(C_ / 128, M_ / 128), 256>>>(attc, Wpc, out, C_);
}

// round 10
// speedup vs baseline: 3.1184x; 2.0450x over previous
#include <cuda_runtime.h>
#include <cuda_bf16.h>
#include <cuda_fp16.h>

// Problem constants
constexpr int B_  = 2;
constexpr int T_  = 2048;
constexpr int C_  = 1024;
constexpr int H_  = 16;
constexpr int HS_ = 64;
constexpr int M_  = B_ * T_;      // 4096
constexpr int N1_ = 3 * C_;       // 3072
constexpr int KB_ = 3 * C_;       // split-K' = 3072

// combined softmax scale: c^-0.5 * log2(e), folded into Q at GEMM1 epilogue
constexpr float QSC_ = 0.03125f * 1.4426950408889634f;

// Scratch (device globals: allocation-free rule)
__device__ float g_att[M_ * C_];             // fp32 attention out [4096,1024]
__device__ __half g_qkvh[M_ * N1_];          // fp16 qkv [4096,3072] (K|Q|V), Q pre-scaled
__device__ __nv_bfloat16 g_Xc  [M_  * KB_];  // X split   [4096,3072]  (hi|hi|lo)
__device__ __nv_bfloat16 g_attc[M_  * KB_];  // att split [4096,3072]
__device__ __nv_bfloat16 g_Wqc [N1_ * KB_];  // W_qkv^T split [3072,3072] (hi|lo|hi)
__device__ __nv_bfloat16 g_Wpc [C_  * KB_];  // W_proj^T split [1024,3072]

// ---------------------------------------------------------------------------
// PTX helpers (baseline ISA only: must compile for virtual compute_103)
// ---------------------------------------------------------------------------
__device__ __forceinline__ unsigned smem_u32(const void* p) {
    unsigned a;
    asm("{ .reg .u64 t; cvta.to.shared.u64 t, %1; cvt.u32.u64 %0, t; }" : "=r"(a) : "l"(p));
    return a;
}
__device__ __forceinline__ void ldm4(unsigned* r, unsigned addr) {
    asm volatile("ldmatrix.sync.aligned.m8n8.x4.shared.b16 {%0,%1,%2,%3}, [%4];"
                 : "=r"(r[0]), "=r"(r[1]), "=r"(r[2]), "=r"(r[3]) : "r"(addr));
}
__device__ __forceinline__ void ldm4t(unsigned* r, unsigned addr) {
    asm volatile("ldmatrix.sync.aligned.m8n8.x4.trans.shared.b16 {%0,%1,%2,%3}, [%4];"
                 : "=r"(r[0]), "=r"(r[1]), "=r"(r[2]), "=r"(r[3]) : "r"(addr));
}
__device__ __forceinline__ void mma_bf16(float* c, const unsigned* a,
                                         unsigned b0, unsigned b1) {
    asm volatile("mma.sync.aligned.m16n8k16.row.col.f32.bf16.bf16.f32 "
                 "{%0,%1,%2,%3}, {%4,%5,%6,%7}, {%8,%9}, {%0,%1,%2,%3};"
                 : "+f"(c[0]), "+f"(c[1]), "+f"(c[2]), "+f"(c[3])
                 : "r"(a[0]), "r"(a[1]), "r"(a[2]), "r"(a[3]), "r"(b0), "r"(b1));
}
__device__ __forceinline__ void mma_f16(float* c, const unsigned* a,
                                        unsigned b0, unsigned b1) {
    asm volatile("mma.sync.aligned.m16n8k16.row.col.f32.f16.f16.f32 "
                 "{%0,%1,%2,%3}, {%4,%5,%6,%7}, {%8,%9}, {%0,%1,%2,%3};"
                 : "+f"(c[0]), "+f"(c[1]), "+f"(c[2]), "+f"(c[3])
                 : "r"(a[0]), "r"(a[1]), "r"(a[2]), "r"(a[3]), "r"(b0), "r"(b1));
}
__device__ __forceinline__ void cpasync16(unsigned dst, const void* src) {
    asm volatile("cp.async.cg.shared.global [%0], [%1], 16;" :: "r"(dst), "l"(src));
}
__device__ __forceinline__ float ex2(float x) {
    float y; asm("ex2.approx.f32 %0, %1;" : "=f"(y) : "f"(x)); return y;
}
__device__ __forceinline__ unsigned h2pack(float lo, float hi) {
    __half2 h = __floats2half2_rn(lo, hi);
    return *(unsigned*)&h;
}

// ---------------------------------------------------------------------------
// Conversion kernels: fp32 -> bf16 hi/lo split
// ---------------------------------------------------------------------------
__global__ __launch_bounds__(256)
void conv_split_kernel(const float* __restrict__ in, __nv_bfloat16* __restrict__ out)
{
    int i4 = blockIdx.x * blockDim.x + threadIdx.x;   // over M_*C_/4
    int r  = i4 >> 8;
    int c4 = (i4 & 255) * 4;
    float4 v = *(const float4*)(in + (size_t)r * C_ + c4);
    __nv_bfloat16 hx = __float2bfloat16_rn(v.x), hy = __float2bfloat16_rn(v.y);
    __nv_bfloat16 hz = __float2bfloat16_rn(v.z), hw = __float2bfloat16_rn(v.w);
    __nv_bfloat162 h01 = __halves2bfloat162(hx, hy);
    __nv_bfloat162 h23 = __halves2bfloat162(hz, hw);
    __nv_bfloat162 l01 = __halves2bfloat162(
        __float2bfloat16_rn(v.x - __bfloat162float(hx)),
        __float2bfloat16_rn(v.y - __bfloat162float(hy)));
    __nv_bfloat162 l23 = __halves2bfloat162(
        __float2bfloat16_rn(v.z - __bfloat162float(hz)),
        __float2bfloat16_rn(v.w - __bfloat162float(hw)));
    size_t ob = (size_t)r * KB_ + c4;
    *(__nv_bfloat162*)(out + ob)              = h01;
    *(__nv_bfloat162*)(out + ob + 2)          = h23;
    *(__nv_bfloat162*)(out + ob + C_)         = h01;
    *(__nv_bfloat162*)(out + ob + C_ + 2)     = h23;
    *(__nv_bfloat162*)(out + ob + 2 * C_)     = l01;
    *(__nv_bfloat162*)(out + ob + 2 * C_ + 2) = l23;
}

// W [K,N] row-major -> out [N, 3K] bf16 with blocks [hi | lo | hi] along K
__global__ __launch_bounds__(256)
void conv_wT_kernel(const float* __restrict__ in, __nv_bfloat16* __restrict__ out,
                    int K, int N)
{
    __shared__ float ts[32][33];
    int n0 = blockIdx.x * 32, k0 = blockIdx.y * 32;
    int tx = threadIdx.x, ty = threadIdx.y;  // 32x8
    #pragma unroll
    for (int i = 0; i < 32; i += 8)
        ts[ty + i][tx] = in[(size_t)(k0 + ty + i) * N + n0 + tx];
    __syncthreads();
    #pragma unroll
    for (int i = 0; i < 32; i += 8) {
        int n = n0 + ty + i, k = k0 + tx;
        float v = ts[tx][ty + i];
        __nv_bfloat16 h = __float2bfloat16_rn(v);
        __nv_bfloat16 l = __float2bfloat16_rn(v - __bfloat162float(h));
        size_t ob = (size_t)n * KB_;
        out[ob + k]         = h;
        out[ob + K + k]     = l;
        out[ob + 2 * K + k] = h;
    }
}

// ---------------------------------------------------------------------------
// Tensor-core GEMM via mma.sync (bf16 split, fp32 accum):
//   C[M,N] = A'[M,KB] @ B'[N,KB]^T.  128x128 CTA tile, BK=32, 8 warps.
// Output: fp32 (Cm) or fp16 (Ch, with Q-segment pre-scale for attention).
// ---------------------------------------------------------------------------
constexpr int LDA_ = 40;   // bf16 stride (80B): conflict-free ldmatrix

__global__ __launch_bounds__(256)
void gemm_mma_kernel(const __nv_bfloat16* __restrict__ A,
                     const __nv_bfloat16* __restrict__ Bm,
                     float* __restrict__ Cm, __half* __restrict__ Ch, int N)
{
    __shared__ __align__(16) __nv_bfloat16 smA[2][128 * LDA_];
    __shared__ __align__(16) __nv_bfloat16 smB[2][128 * LDA_];

    const int tid = threadIdx.x, lane = tid & 31, wid = tid >> 5;
    const int wm = (wid & 1) * 64, wn = (wid >> 1) * 32;
    const int bm = blockIdx.y * 128, bn = blockIdx.x * 128;

    const __nv_bfloat16* Ag = A  + (size_t)bm * KB_;
    const __nv_bfloat16* Bg = Bm + (size_t)bn * KB_;

    const int lr = tid >> 2, lseg = tid & 3;

    float acc[4][4][4] = {};

    #pragma unroll
    for (int u = 0; u < 2; u++) {
        int row = lr + u * 64;
        *(uint4*)&smA[0][row * LDA_ + lseg * 8] =
            *(const uint4*)(Ag + (size_t)row * KB_ + lseg * 8);
        *(uint4*)&smB[0][row * LDA_ + lseg * 8] =
            *(const uint4*)(Bg + (size_t)row * KB_ + lseg * 8);
    }
    __syncthreads();

    const unsigned baseA[2] = { smem_u32(smA[0]), smem_u32(smA[1]) };
    const unsigned baseB[2] = { smem_u32(smB[0]), smem_u32(smB[1]) };
    const int ar = lane & 15, ah = lane >> 4;
    const int bg = lane >> 3, bi = lane & 7;

    constexpr int NK = KB_ / 32;                 // 96
    for (int kt = 0; kt < NK; kt++) {
        const int cur = kt & 1, nxt = cur ^ 1;
        uint4 ra[2], rb[2];
        const bool pf = (kt + 1 < NK);
        if (pf) {
            const int kpos = (kt + 1) * 32;
            #pragma unroll
            for (int u = 0; u < 2; u++) {
                int row = lr + u * 64;
                ra[u] = *(const uint4*)(Ag + (size_t)row * KB_ + kpos + lseg * 8);
                rb[u] = *(const uint4*)(Bg + (size_t)row * KB_ + kpos + lseg * 8);
            }
        }

        #pragma unroll
        for (int ks = 0; ks < 2; ks++) {
            unsigned afr[4][4], bfr[2][4];
            #pragma unroll
            for (int mt = 0; mt < 4; mt++) {
                unsigned ad = baseA[cur] +
                    ((wm + mt * 16 + ar) * LDA_ + ks * 16 + ah * 8) * 2;
                ldm4(afr[mt], ad);
            }
            #pragma unroll
            for (int p = 0; p < 2; p++) {
                unsigned bd = baseB[cur] +
                    ((wn + p * 16 + (bg >> 1) * 8 + bi) * LDA_ + ks * 16 + (bg & 1) * 8) * 2;
                ldm4(bfr[p], bd);
            }
            #pragma unroll
            for (int mt = 0; mt < 4; mt++)
                #pragma unroll
                for (int ng = 0; ng < 4; ng++)
                    mma_bf16(acc[mt][ng], afr[mt],
                             bfr[ng >> 1][(ng & 1) * 2], bfr[ng >> 1][(ng & 1) * 2 + 1]);
        }

        if (pf) {
            #pragma unroll
            for (int u = 0; u < 2; u++) {
                int row = lr + u * 64;
                *(uint4*)&smA[nxt][row * LDA_ + lseg * 8] = ra[u];
                *(uint4*)&smB[nxt][row * LDA_ + lseg * 8] = rb[u];
            }
        }
        __syncthreads();
    }

    if (Ch) {
        // fp16 output, Q-segment (cols [1024,2048)) scaled by QSC_
        #pragma unroll
        for (int mt = 0; mt < 4; mt++)
            #pragma unroll
            for (int ng = 0; ng < 4; ng++) {
                int col = bn + wn + ng * 8 + (lane & 3) * 2;
                float qs = (col >= C_ && col < 2 * C_) ? QSC_ : 1.0f;
                int row = bm + wm + mt * 16 + (lane >> 2);
                __half* cp = Ch + (size_t)row * N + col;
                *(__half2*)cp =
                    __floats2half2_rn(acc[mt][ng][0] * qs, acc[mt][ng][1] * qs);
                *(__half2*)(cp + (size_t)8 * N) =
                    __floats2half2_rn(acc[mt][ng][2] * qs, acc[mt][ng][3] * qs);
            }
    } else {
        #pragma unroll
        for (int mt = 0; mt < 4; mt++)
            #pragma unroll
            for (int ng = 0; ng < 4; ng++) {
                float* cp = Cm + (size_t)(bm + wm + mt * 16 + (lane >> 2)) * N
                               + bn + wn + ng * 8 + (lane & 3) * 2;
                *(float2*)cp = make_float2(acc[mt][ng][0], acc[mt][ng][1]);
                *(float2*)(cp + (size_t)8 * N) = make_float2(acc[mt][ng][2], acc[mt][ng][3]);
            }
    }
}

// ---------------------------------------------------------------------------
// Tensor-core causal flash attention (fp16 mma, fp32 softmax/accum).
// Grid (T/64, B*H), 128 threads = 4 warps; warp w owns q-rows [16w,16w+16).
// Q pre-scaled by c^-0.5*log2e, so S fragments are directly exp2 arguments.
// qkvh layout [B,T,3C]: K|Q|V per head h at col h*64 (+0 / +C_ / +2C_).
// ---------------------------------------------------------------------------
constexpr int LDH = 72;   // fp16 row stride (144B): conflict-free ldmatrix

__global__ __launch_bounds__(128)
void attn_mma_kernel(const __half* __restrict__ qkvh, float* __restrict__ outp)
{
    __shared__ __align__(16) __half Qs[64 * LDH];
    __shared__ __align__(16) __half Ks[2][64 * LDH];
    __shared__ __align__(16) __half Vsm[2][64 * LDH];

    const int qb  = (int)gridDim.x - 1 - (int)blockIdx.x;   // heavy first
    const int bh  = blockIdx.y, b = bh >> 4, h = bh & 15;
    const int tid = threadIdx.x, lane = tid & 31, wid = tid >> 5;
    const int wrow = wid * 16;
    const size_t tok0 = (size_t)b * T_;
    const int qtok0 = qb * 64;

    // Load Q tile (64x64 fp16) to smem
    {
        const __half* src = qkvh + (tok0 + qtok0) * N1_ + C_ + h * HS_;
        #pragma unroll
        for (int u = 0; u < 4; u++) {
            int chunk = tid + u * 128;
            int r = chunk >> 3, sg = chunk & 7;
            *(uint4*)&Qs[r * LDH + sg * 8] = *(const uint4*)(src + (size_t)r * N1_ + sg * 8);
        }
    }

    auto issue_kv = [&](int kb, int buf) {
        const __half* ks = qkvh + (tok0 + kb * 64) * N1_ + h * HS_;
        const __half* vs = ks + 2 * C_;
        unsigned kd = smem_u32(Ks[buf]), vd = smem_u32(Vsm[buf]);
        #pragma unroll
        for (int u = 0; u < 4; u++) {
            int chunk = tid + u * 128;
            int r = chunk >> 3, sg = chunk & 7;
            unsigned so = (r * LDH + sg * 8) * 2;
            cpasync16(kd + so, ks + (size_t)r * N1_ + sg * 8);
            cpasync16(vd + so, vs + (size_t)r * N1_ + sg * 8);
        }
        asm volatile("cp.async.commit_group;" ::: "memory");
    };
    issue_kv(0, 0);

    __syncthreads();   // Qs ready

    // Build Q A-fragments (held in registers for whole kernel)
    const int roff = (lane & 7) + ((lane & 8) ? 8 : 0);
    const int coff = (lane & 16) ? 8 : 0;
    unsigned qa[4][4];
    #pragma unroll
    for (int ks = 0; ks < 4; ks++)
        ldm4(qa[ks], smem_u32(Qs) + (unsigned)(((wrow + roff) * LDH + ks * 16 + coff) * 2));

    float O[8][4];
    #pragma unroll
    for (int j = 0; j < 8; j++)
        #pragma unroll
        for (int c = 0; c < 4; c++) O[j][c] = 0.0f;
    float mz0 = -1e30f, mz1 = -1e30f, l0 = 0.0f, l1 = 0.0f;
    const int qr0 = wrow + (lane >> 2);      // local row in [0,64)
    const int qr1 = qr0 + 8;

    for (int kb = 0; kb <= qb; kb++) {
        const int buf = kb & 1;
        if (kb < qb) {
            issue_kv(kb + 1, buf ^ 1);
            asm volatile("cp.async.wait_group 1;" ::: "memory");
        } else {
            asm volatile("cp.async.wait_group 0;" ::: "memory");
        }
        __syncthreads();

        // S = Q @ K^T  (already in exp2-scaled units via Q pre-scale)
        float S[8][4];
        #pragma unroll
        for (int j = 0; j < 8; j++)
            #pragma unroll
            for (int c = 0; c < 4; c++) S[j][c] = 0.0f;

        const unsigned kbase = smem_u32(Ks[buf]);
        #pragma unroll
        for (int kg = 0; kg < 4; kg++)
            #pragma unroll
            for (int ng = 0; ng < 4; ng++) {
                unsigned r[4];
                ldm4(r, kbase + (unsigned)(((16 * ng + roff) * LDH + 16 * kg + coff) * 2));
                mma_f16(S[2 * ng],     qa[kg], r[0], r[2]);
                mma_f16(S[2 * ng + 1], qa[kg], r[1], r[3]);
            }

        // Causal mask (only diagonal block partial)
        if (kb == qb) {
            #pragma unroll
            for (int j = 0; j < 8; j++) {
                int k0 = 8 * j + 2 * (lane & 3);
                if (k0     > qr0) S[j][0] = -1e30f;
                if (k0 + 1 > qr0) S[j][1] = -1e30f;
                if (k0     > qr1) S[j][2] = -1e30f;
                if (k0 + 1 > qr1) S[j][3] = -1e30f;
            }
        }

        // Online softmax (base-2)
        float mx0 = -1e30f, mx1 = -1e30f;
        #pragma unroll
        for (int j = 0; j < 8; j++) {
            mx0 = fmaxf(mx0, fmaxf(S[j][0], S[j][1]));
            mx1 = fmaxf(mx1, fmaxf(S[j][2], S[j][3]));
        }
        mx0 = fmaxf(mx0, __shfl_xor_sync(0xffffffffu, mx0, 1));
        mx0 = fmaxf(mx0, __shfl_xor_sync(0xffffffffu, mx0, 2));
        mx1 = fmaxf(mx1, __shfl_xor_sync(0xffffffffu, mx1, 1));
        mx1 = fmaxf(mx1, __shfl_xor_sync(0xffffffffu, mx1, 2));
        const float mn0 = fmaxf(mz0, mx0), mn1 = fmaxf(mz1, mx1);
        const float f0 = ex2(mz0 - mn0), f1 = ex2(mz1 - mn1);
        mz0 = mn0; mz1 = mn1;

        float s0 = 0.0f, s1 = 0.0f;
        #pragma unroll
        for (int j = 0; j < 8; j++) {
            S[j][0] = ex2(S[j][0] - mn0); s0 += S[j][0];
            S[j][1] = ex2(S[j][1] - mn0); s0 += S[j][1];
            S[j][2] = ex2(S[j][2] - mn1); s1 += S[j][2];
            S[j][3] = ex2(S[j][3] - mn1); s1 += S[j][3];
        }
        s0 += __shfl_xor_sync(0xffffffffu, s0, 1);
        s0 += __shfl_xor_sync(0xffffffffu, s0, 2);
        s1 += __shfl_xor_sync(0xffffffffu, s1, 1);
        s1 += __shfl_xor_sync(0xffffffffu, s1, 2);
        l0 = l0 * f0 + s0;
        l1 = l1 * f1 + s1;
        #pragma unroll
        for (int j = 0; j < 8; j++) {
            O[j][0] *= f0; O[j][1] *= f0;
            O[j][2] *= f1; O[j][3] *= f1;
        }

        // O += P @ V  (P fragments built in registers from S)
        const unsigned vbase = smem_u32(Vsm[buf]);
        #pragma unroll
        for (int kg = 0; kg < 4; kg++) {
            unsigned ap[4];
            ap[0] = h2pack(S[2 * kg][0],     S[2 * kg][1]);
            ap[1] = h2pack(S[2 * kg][2],     S[2 * kg][3]);
            ap[2] = h2pack(S[2 * kg + 1][0], S[2 * kg + 1][1]);
            ap[3] = h2pack(S[2 * kg + 1][2], S[2 * kg + 1][3]);
            #pragma unroll
            for (int dg = 0; dg < 4; dg++) {
                unsigned r[4];
                ldm4t(r, vbase + (unsigned)(((16 * kg + roff) * LDH + 16 * dg + coff) * 2));
                mma_f16(O[2 * dg],     ap, r[0], r[1]);
                mma_f16(O[2 * dg + 1], ap, r[2], r[3]);
            }
        }
        __syncthreads();   // safe to overwrite buf next iteration
    }

    // Normalize and store fp32
    const float inv0 = 1.0f / l0, inv1 = 1.0f / l1;
    float* op0 = outp + (tok0 + qtok0 + qr0) * C_ + h * HS_ + 2 * (lane & 3);
    float* op1 = op0 + (size_t)8 * C_;
    #pragma unroll
    for (int j = 0; j < 8; j++) {
        *(float2*)(op0 + 8 * j) = make_float2(O[j][0] * inv0, O[j][1] * inv0);
        *(float2*)(op1 + 8 * j) = make_float2(O[j][2] * inv1, O[j][3] * inv1);
    }
}

// ---------------------------------------------------------------------------
// Launch
// ---------------------------------------------------------------------------
extern "C" void kernel_launch(void* const* d_in, const int* in_sizes, int n_in,
                              void* d_out, int out_size)
{
    const float* X = nullptr; const float* Wqkv = nullptr; const float* Wproj = nullptr;
    for (int i = 0; i < n_in; i++) {
        if      (in_sizes[i] == M_ * C_)   X     = (const float*)d_in[i];
        else if (in_sizes[i] == C_ * N1_)  Wqkv  = (const float*)d_in[i];
        else if (in_sizes[i] == C_ * C_)   Wproj = (const float*)d_in[i];
    }
    float* out = (float*)d_out;

    float* att_buf;
    __half* qkvh;
    __nv_bfloat16 *Xc, *attc, *Wqc, *Wpc;
    cudaGetSymbolAddress((void**)&att_buf, g_att);
    cudaGetSymbolAddress((void**)&qkvh, g_qkvh);
    cudaGetSymbolAddress((void**)&Xc,   g_Xc);
    cudaGetSymbolAddress((void**)&attc, g_attc);
    cudaGetSymbolAddress((void**)&Wqc,  g_Wqc);
    cudaGetSymbolAddress((void**)&Wpc,  g_Wpc);

    // 1) split-convert inputs
    conv_split_kernel<<<M_ * C_ / 4 / 256, 256>>>(X, Xc);
    conv_wT_kernel<<<dim3(N1_ / 32, C_ / 32), dim3(32, 8)>>>(Wqkv, Wqc, C_, N1_);
    conv_wT_kernel<<<dim3(C_ / 32,  C_ / 32), dim3(32, 8)>>>(Wproj, Wpc, C_, C_);

    // 2) qkv = X @ W_qkv -> fp16 (Q segment pre-scaled)
    gemm_mma_kernel<<<dim3(N1_ / 128, M_ / 128), 256>>>(Xc, Wqc, nullptr, qkvh, N1_);

    // 3) tensor-core flash attention -> fp32 att_buf
    attn_mma_kernel<<<dim3(T_ / 64, B_ * H_), 128>>>(qkvh, att_buf);

    // 4) split-convert attention output, then out = att @ W_proj (fp32 out)
    conv_split_kernel<<<M_ * C_ / 4 / 256, 256>>>(att_buf, attc);
    gemm_mma_kernel<<<dim3(C_ / 128, M_ / 128), 256>>>(attc, Wpc, out, nullptr, C_);
}

// round 12
// speedup vs baseline: 6.3911x; 2.0495x over previous
#include <cuda_runtime.h>
#include <cuda_fp16.h>

// Problem constants
constexpr int B_  = 2;
constexpr int T_  = 2048;
constexpr int C_  = 1024;
constexpr int H_  = 16;
constexpr int HS_ = 64;
constexpr int M_  = B_ * T_;      // 4096
constexpr int N1_ = 3 * C_;       // 3072

// combined softmax scale: c^-0.5 * log2(e), folded into Q at GEMM1 epilogue
constexpr float QSC_ = 0.03125f * 1.4426950408889634f;

// Scratch (device globals: allocation-free rule)
__device__ __half g_qkvh[M_ * N1_];   // fp16 qkv [4096,3072] (K|Q|V), Q pre-scaled
__device__ __half g_atth[M_ * C_];    // fp16 attention out [4096,1024]
__device__ __half g_Xh  [M_  * C_];   // X fp16 [4096,1024]
__device__ __half g_WqT [N1_ * C_];   // W_qkv^T fp16 [3072,1024]
__device__ __half g_WpT [C_  * C_];   // W_proj^T fp16 [1024,1024]

// ---------------------------------------------------------------------------
// PTX helpers (baseline ISA only: must compile for virtual compute_103)
// ---------------------------------------------------------------------------
__device__ __forceinline__ unsigned smem_u32(const void* p) {
    unsigned a;
    asm("{ .reg .u64 t; cvta.to.shared.u64 t, %1; cvt.u32.u64 %0, t; }" : "=r"(a) : "l"(p));
    return a;
}
__device__ __forceinline__ void ldm4(unsigned* r, unsigned addr) {
    asm volatile("ldmatrix.sync.aligned.m8n8.x4.shared.b16 {%0,%1,%2,%3}, [%4];"
                 : "=r"(r[0]), "=r"(r[1]), "=r"(r[2]), "=r"(r[3]) : "r"(addr));
}
__device__ __forceinline__ void ldm4t(unsigned* r, unsigned addr) {
    asm volatile("ldmatrix.sync.aligned.m8n8.x4.trans.shared.b16 {%0,%1,%2,%3}, [%4];"
                 : "=r"(r[0]), "=r"(r[1]), "=r"(r[2]), "=r"(r[3]) : "r"(addr));
}
__device__ __forceinline__ void mma_f16(float* c, const unsigned* a,
                                        unsigned b0, unsigned b1) {
    asm volatile("mma.sync.aligned.m16n8k16.row.col.f32.f16.f16.f32 "
                 "{%0,%1,%2,%3}, {%4,%5,%6,%7}, {%8,%9}, {%0,%1,%2,%3};"
                 : "+f"(c[0]), "+f"(c[1]), "+f"(c[2]), "+f"(c[3])
                 : "r"(a[0]), "r"(a[1]), "r"(a[2]), "r"(a[3]), "r"(b0), "r"(b1));
}
__device__ __forceinline__ void cpasync16(unsigned dst, const void* src) {
    asm volatile("cp.async.cg.shared.global [%0], [%1], 16;" :: "r"(dst), "l"(src));
}
__device__ __forceinline__ float ex2(float x) {
    float y; asm("ex2.approx.f32 %0, %1;" : "=f"(y) : "f"(x)); return y;
}
__device__ __forceinline__ unsigned h2pack(float lo, float hi) {
    __half2 h = __floats2half2_rn(lo, hi);
    return *(unsigned*)&h;
}

// ---------------------------------------------------------------------------
// Conversion kernels: fp32 -> fp16
// ---------------------------------------------------------------------------
__global__ __launch_bounds__(256)
void conv_f2h_kernel(const float* __restrict__ in, __half* __restrict__ out)
{
    int i = blockIdx.x * blockDim.x + threadIdx.x;   // over n/4 float4s
    float4 v = ((const float4*)in)[i];
    ((__half2*)out)[2 * i]     = __floats2half2_rn(v.x, v.y);
    ((__half2*)out)[2 * i + 1] = __floats2half2_rn(v.z, v.w);
}

// W [K,N] row-major (K=C_) -> out [N, C_] fp16 transposed
__global__ __launch_bounds__(256)
void conv_wT_h_kernel(const float* __restrict__ in, __half* __restrict__ out, int N)
{
    __shared__ float ts[32][33];
    int n0 = blockIdx.x * 32, k0 = blockIdx.y * 32;
    int tx = threadIdx.x, ty = threadIdx.y;  // 32x8
    #pragma unroll
    for (int i = 0; i < 32; i += 8)
        ts[ty + i][tx] = in[(size_t)(k0 + ty + i) * N + n0 + tx];
    __syncthreads();
    #pragma unroll
    for (int i = 0; i < 32; i += 8) {
        int n = n0 + ty + i, k = k0 + tx;
        out[(size_t)n * C_ + k] = __float2half_rn(ts[tx][ty + i]);
    }
}

// ---------------------------------------------------------------------------
// Tensor-core GEMM via mma.sync (fp16 in, fp32 accum), K = C_ = 1024:
//   C[M,N] = A[M,C_] @ B[N,C_]^T.  128x128 CTA tile, BK=32, 8 warps.
// Output: fp32 (Cm) or fp16 (Ch, with Q-segment pre-scale for attention).
// ---------------------------------------------------------------------------
constexpr int LDA_ = 40;   // fp16 stride (80B): conflict-free ldmatrix

__global__ __launch_bounds__(256)
void gemm_mma_h_kernel(const __half* __restrict__ A,
                       const __half* __restrict__ Bm,
                       float* __restrict__ Cm, __half* __restrict__ Ch, int N)
{
    __shared__ __align__(16) __half smA[2][128 * LDA_];
    __shared__ __align__(16) __half smB[2][128 * LDA_];

    const int tid = threadIdx.x, lane = tid & 31, wid = tid >> 5;
    const int wm = (wid & 1) * 64, wn = (wid >> 1) * 32;
    const int bm = blockIdx.y * 128, bn = blockIdx.x * 128;

    const __half* Ag = A  + (size_t)bm * C_;
    const __half* Bg = Bm + (size_t)bn * C_;

    const int lr = tid >> 2, lseg = tid & 3;

    float acc[4][4][4] = {};

    #pragma unroll
    for (int u = 0; u < 2; u++) {
        int row = lr + u * 64;
        *(uint4*)&smA[0][row * LDA_ + lseg * 8] =
            *(const uint4*)(Ag + (size_t)row * C_ + lseg * 8);
        *(uint4*)&smB[0][row * LDA_ + lseg * 8] =
            *(const uint4*)(Bg + (size_t)row * C_ + lseg * 8);
    }
    __syncthreads();

    const unsigned baseA[2] = { smem_u32(smA[0]), smem_u32(smA[1]) };
    const unsigned baseB[2] = { smem_u32(smB[0]), smem_u32(smB[1]) };
    const int ar = lane & 15, ah = lane >> 4;
    const int bg = lane >> 3, bi = lane & 7;

    constexpr int NK = C_ / 32;                  // 32
    for (int kt = 0; kt < NK; kt++) {
        const int cur = kt & 1, nxt = cur ^ 1;
        uint4 ra[2], rb[2];
        const bool pf = (kt + 1 < NK);
        if (pf) {
            const int kpos = (kt + 1) * 32;
            #pragma unroll
            for (int u = 0; u < 2; u++) {
                int row = lr + u * 64;
                ra[u] = *(const uint4*)(Ag + (size_t)row * C_ + kpos + lseg * 8);
                rb[u] = *(const uint4*)(Bg + (size_t)row * C_ + kpos + lseg * 8);
            }
        }

        #pragma unroll
        for (int ks = 0; ks < 2; ks++) {
            unsigned afr[4][4], bfr[2][4];
            #pragma unroll
            for (int mt = 0; mt < 4; mt++) {
                unsigned ad = baseA[cur] +
                    ((wm + mt * 16 + ar) * LDA_ + ks * 16 + ah * 8) * 2;
                ldm4(afr[mt], ad);
            }
            #pragma unroll
            for (int p = 0; p < 2; p++) {
                unsigned bd = baseB[cur] +
                    ((wn + p * 16 + (bg >> 1) * 8 + bi) * LDA_ + ks * 16 + (bg & 1) * 8) * 2;
                ldm4(bfr[p], bd);
            }
            #pragma unroll
            for (int mt = 0; mt < 4; mt++)
                #pragma unroll
                for (int ng = 0; ng < 4; ng++)
                    mma_f16(acc[mt][ng], afr[mt],
                            bfr[ng >> 1][(ng & 1) * 2], bfr[ng >> 1][(ng & 1) * 2 + 1]);
        }

        if (pf) {
            #pragma unroll
            for (int u = 0; u < 2; u++) {
                int row = lr + u * 64;
                *(uint4*)&smA[nxt][row * LDA_ + lseg * 8] = ra[u];
                *(uint4*)&smB[nxt][row * LDA_ + lseg * 8] = rb[u];
            }
        }
        __syncthreads();
    }

    if (Ch) {
        // fp16 output, Q-segment (cols [1024,2048)) scaled by QSC_
        #pragma unroll
        for (int mt = 0; mt < 4; mt++)
            #pragma unroll
            for (int ng = 0; ng < 4; ng++) {
                int col = bn + wn + ng * 8 + (lane & 3) * 2;
                float qs = (col >= C_ && col < 2 * C_) ? QSC_ : 1.0f;
                int row = bm + wm + mt * 16 + (lane >> 2);
                __half* cp = Ch + (size_t)row * N + col;
                *(__half2*)cp =
                    __floats2half2_rn(acc[mt][ng][0] * qs, acc[mt][ng][1] * qs);
                *(__half2*)(cp + (size_t)8 * N) =
                    __floats2half2_rn(acc[mt][ng][2] * qs, acc[mt][ng][3] * qs);
            }
    } else {
        #pragma unroll
        for (int mt = 0; mt < 4; mt++)
            #pragma unroll
            for (int ng = 0; ng < 4; ng++) {
                float* cp = Cm + (size_t)(bm + wm + mt * 16 + (lane >> 2)) * N
                               + bn + wn + ng * 8 + (lane & 3) * 2;
                *(float2*)cp = make_float2(acc[mt][ng][0], acc[mt][ng][1]);
                *(float2*)(cp + (size_t)8 * N) = make_float2(acc[mt][ng][2], acc[mt][ng][3]);
            }
    }
}

// ---------------------------------------------------------------------------
// Tensor-core causal flash attention (fp16 mma, fp32 softmax/accum).
// Grid (T/64, B*H), 128 threads = 4 warps; warp w owns q-rows [16w,16w+16).
// Q pre-scaled by c^-0.5*log2e, so S fragments are directly exp2 arguments.
// qkvh layout [B,T,3C]: K|Q|V per head h at col h*64 (+0 / +C_ / +2C_).
// Output: fp16 (consumed by proj GEMM).
// ---------------------------------------------------------------------------
constexpr int LDH = 72;   // fp16 row stride (144B): conflict-free ldmatrix

__global__ __launch_bounds__(128)
void attn_mma_kernel(const __half* __restrict__ qkvh, __half* __restrict__ outp)
{
    __shared__ __align__(16) __half Qs[64 * LDH];
    __shared__ __align__(16) __half Ks[2][64 * LDH];
    __shared__ __align__(16) __half Vsm[2][64 * LDH];

    const int qb  = (int)gridDim.x - 1 - (int)blockIdx.x;   // heavy first
    const int bh  = blockIdx.y, b = bh >> 4, h = bh & 15;
    const int tid = threadIdx.x, lane = tid & 31, wid = tid >> 5;
    const int wrow = wid * 16;
    const size_t tok0 = (size_t)b * T_;
    const int qtok0 = qb * 64;

    // Load Q tile (64x64 fp16) to smem
    {
        const __half* src = qkvh + (tok0 + qtok0) * N1_ + C_ + h * HS_;
        #pragma unroll
        for (int u = 0; u < 4; u++) {
            int chunk = tid + u * 128;
            int r = chunk >> 3, sg = chunk & 7;
            *(uint4*)&Qs[r * LDH + sg * 8] = *(const uint4*)(src + (size_t)r * N1_ + sg * 8);
        }
    }

    auto issue_kv = [&](int kb, int buf) {
        const __half* ks = qkvh + (tok0 + kb * 64) * N1_ + h * HS_;
        const __half* vs = ks + 2 * C_;
        unsigned kd = smem_u32(Ks[buf]), vd = smem_u32(Vsm[buf]);
        #pragma unroll
        for (int u = 0; u < 4; u++) {
            int chunk = tid + u * 128;
            int r = chunk >> 3, sg = chunk & 7;
            unsigned so = (r * LDH + sg * 8) * 2;
            cpasync16(kd + so, ks + (size_t)r * N1_ + sg * 8);
            cpasync16(vd + so, vs + (size_t)r * N1_ + sg * 8);
        }
        asm volatile("cp.async.commit_group;" ::: "memory");
    };
    issue_kv(0, 0);

    __syncthreads();   // Qs ready

    // Build Q A-fragments (held in registers for whole kernel)
    const int roff = (lane & 7) + ((lane & 8) ? 8 : 0);
    const int coff = (lane & 16) ? 8 : 0;
    unsigned qa[4][4];
    #pragma unroll
    for (int ks = 0; ks < 4; ks++)
        ldm4(qa[ks], smem_u32(Qs) + (unsigned)(((wrow + roff) * LDH + ks * 16 + coff) * 2));

    float O[8][4];
    #pragma unroll
    for (int j = 0; j < 8; j++)
        #pragma unroll
        for (int c = 0; c < 4; c++) O[j][c] = 0.0f;
    float mz0 = -1e30f, mz1 = -1e30f, l0 = 0.0f, l1 = 0.0f;
    const int qr0 = wrow + (lane >> 2);      // local row in [0,64)
    const int qr1 = qr0 + 8;

    for (int kb = 0; kb <= qb; kb++) {
        const int buf = kb & 1;
        if (kb < qb) {
            issue_kv(kb + 1, buf ^ 1);
            asm volatile("cp.async.wait_group 1;" ::: "memory");
        } else {
            asm volatile("cp.async.wait_group 0;" ::: "memory");
        }
        __syncthreads();

        // S = Q @ K^T  (already in exp2-scaled units via Q pre-scale)
        float S[8][4];
        #pragma unroll
        for (int j = 0; j < 8; j++)
            #pragma unroll
            for (int c = 0; c < 4; c++) S[j][c] = 0.0f;

        const unsigned kbase = smem_u32(Ks[buf]);
        #pragma unroll
        for (int kg = 0; kg < 4; kg++)
            #pragma unroll
            for (int ng = 0; ng < 4; ng++) {
                unsigned r[4];
                ldm4(r, kbase + (unsigned)(((16 * ng + roff) * LDH + 16 * kg + coff) * 2));
                mma_f16(S[2 * ng],     qa[kg], r[0], r[2]);
                mma_f16(S[2 * ng + 1], qa[kg], r[1], r[3]);
            }

        // Causal mask (only diagonal block partial)
        if (kb == qb) {
            #pragma unroll
            for (int j = 0; j < 8; j++) {
                int k0 = 8 * j + 2 * (lane & 3);
                if (k0     > qr0) S[j][0] = -1e30f;
                if (k0 + 1 > qr0) S[j][1] = -1e30f;
                if (k0     > qr1) S[j][2] = -1e30f;
                if (k0 + 1 > qr1) S[j][3] = -1e30f;
            }
        }

        // Online softmax (base-2)
        float mx0 = -1e30f, mx1 = -1e30f;
        #pragma unroll
        for (int j = 0; j < 8; j++) {
            mx0 = fmaxf(mx0, fmaxf(S[j][0], S[j][1]));
            mx1 = fmaxf(mx1, fmaxf(S[j][2], S[j][3]));
        }
        mx0 = fmaxf(mx0, __shfl_xor_sync(0xffffffffu, mx0, 1));
        mx0 = fmaxf(mx0, __shfl_xor_sync(0xffffffffu, mx0, 2));
        mx1 = fmaxf(mx1, __shfl_xor_sync(0xffffffffu, mx1, 1));
        mx1 = fmaxf(mx1, __shfl_xor_sync(0xffffffffu, mx1, 2));
        const float mn0 = fmaxf(mz0, mx0), mn1 = fmaxf(mz1, mx1);
        const float f0 = ex2(mz0 - mn0), f1 = ex2(mz1 - mn1);
        mz0 = mn0; mz1 = mn1;

        float s0 = 0.0f, s1 = 0.0f;
        #pragma unroll
        for (int j = 0; j < 8; j++) {
            S[j][0] = ex2(S[j][0] - mn0); s0 += S[j][0];
            S[j][1] = ex2(S[j][1] - mn0); s0 += S[j][1];
            S[j][2] = ex2(S[j][2] - mn1); s1 += S[j][2];
            S[j][3] = ex2(S[j][3] - mn1); s1 += S[j][3];
        }
        s0 += __shfl_xor_sync(0xffffffffu, s0, 1);
        s0 += __shfl_xor_sync(0xffffffffu, s0, 2);
        s1 += __shfl_xor_sync(0xffffffffu, s1, 1);
        s1 += __shfl_xor_sync(0xffffffffu, s1, 2);
        l0 = l0 * f0 + s0;
        l1 = l1 * f1 + s1;
        #pragma unroll
        for (int j = 0; j < 8; j++) {
            O[j][0] *= f0; O[j][1] *= f0;
            O[j][2] *= f1; O[j][3] *= f1;
        }

        // O += P @ V  (P fragments built in registers from S)
        const unsigned vbase = smem_u32(Vsm[buf]);
        #pragma unroll
        for (int kg = 0; kg < 4; kg++) {
            unsigned ap[4];
            ap[0] = h2pack(S[2 * kg][0],     S[2 * kg][1]);
            ap[1] = h2pack(S[2 * kg][2],     S[2 * kg][3]);
            ap[2] = h2pack(S[2 * kg + 1][0], S[2 * kg + 1][1]);
            ap[3] = h2pack(S[2 * kg + 1][2], S[2 * kg + 1][3]);
            #pragma unroll
            for (int dg = 0; dg < 4; dg++) {
                unsigned r[4];
                ldm4t(r, vbase + (unsigned)(((16 * kg + roff) * LDH + 16 * dg + coff) * 2));
                mma_f16(O[2 * dg],     ap, r[0], r[1]);
                mma_f16(O[2 * dg + 1], ap, r[2], r[3]);
            }
        }
        __syncthreads();   // safe to overwrite buf next iteration
    }

    // Normalize and store fp16
    const float inv0 = 1.0f / l0, inv1 = 1.0f / l1;
    __half* op0 = outp + (tok0 + qtok0 + qr0) * C_ + h * HS_ + 2 * (lane & 3);
    __half* op1 = op0 + (size_t)8 * C_;
    #pragma unroll
    for (int j = 0; j < 8; j++) {
        *(__half2*)(op0 + 8 * j) = __floats2half2_rn(O[j][0] * inv0, O[j][1] * inv0);
        *(__half2*)(op1 + 8 * j) = __floats2half2_rn(O[j][2] * inv1, O[j][3] * inv1);
    }
}

// ---------------------------------------------------------------------------
// Launch
// ---------------------------------------------------------------------------
extern "C" void kernel_launch(void* const* d_in, const int* in_sizes, int n_in,
                              void* d_out, int out_size)
{
    const float* X = nullptr; const float* Wqkv = nullptr; const float* Wproj = nullptr;
    for (int i = 0; i < n_in; i++) {
        if      (in_sizes[i] == M_ * C_)   X     = (const float*)d_in[i];
        else if (in_sizes[i] == C_ * N1_)  Wqkv  = (const float*)d_in[i];
        else if (in_sizes[i] == C_ * C_)   Wproj = (const float*)d_in[i];
    }
    float* out = (float*)d_out;

    __half *qkvh, *atth, *Xh, *WqT, *WpT;
    cudaGetSymbolAddress((void**)&qkvh, g_qkvh);
    cudaGetSymbolAddress((void**)&atth, g_atth);
    cudaGetSymbolAddress((void**)&Xh,   g_Xh);
    cudaGetSymbolAddress((void**)&WqT,  g_WqT);
    cudaGetSymbolAddress((void**)&WpT,  g_WpT);

    // 1) convert inputs to fp16 (weights transposed)
    conv_f2h_kernel<<<M_ * C_ / 4 / 256, 256>>>(X, Xh);
    conv_wT_h_kernel<<<dim3(N1_ / 32, C_ / 32), dim3(32, 8)>>>(Wqkv, WqT, N1_);
    conv_wT_h_kernel<<<dim3(C_ / 32,  C_ / 32), dim3(32, 8)>>>(Wproj, WpT, C_);

    // 2) qkv = X @ W_qkv -> fp16 (Q segment pre-scaled), K=1024
    gemm_mma_h_kernel<<<dim3(N1_ / 128, M_ / 128), 256>>>(Xh, WqT, nullptr, qkvh, N1_);

    // 3) tensor-core flash attention -> fp16 atth
    attn_mma_kernel<<<dim3(T_ / 64, B_ * H_), 128>>>(qkvh, atth);

    // 4) out = att @ W_proj (fp32 out), K=1024
    gemm_mma_h_kernel<<<dim3(C_ / 128, M_ / 128), 256>>>(atth, WpT, out, nullptr, C_);
}